// round 13
// baseline (speedup 1.0000x reference)
#include <cuda_runtime.h>
#include <cuda_fp16.h>
#include <math.h>
#include <float.h>

#define NN 100000
#define EE 1600000
#define FIN 256
#define HD 64
#define CD 40
#define NB 98                 // ceil(NN/1024) scan blocks
#define GB1 391               // gemm1 blocks: ceil(NN/256)
#define EB1 1563              // extract blocks: ceil(EE/1024)

// ---- scratch ----------------------------------------------------------------
__device__ __align__(16) float  g_deg[NN];        // deg -> dinv in place
__device__ __align__(16) float  g_H1[NN * HD];    // x@W1 fp32 (self term)
__device__ __align__(16) __half g_H1h[NN * HD];   // x@W1 fp16 (gather)
__device__ __align__(16) float  g_H1b[NN * HD];   // relu(agg1) fp32
__device__ __align__(16) float  g_H2[NN * CD];    // h1b@W2 fp32 (self term)
__device__ __align__(16) __half g_H2h[NN * CD];   // h1b@W2 fp16 (gather)
__device__ int   g_src[EE];
__device__ int   g_dst[EE];
__device__ int   g_cnt[NN];
__device__ int   g_cur[NN];
__device__ int   g_rowptr[NN + 1];
__device__ int   g_bsum[128];
__device__ __align__(16) int2 g_csr_sn[EE];       // (src, norm-bits) in CSR order

// ---------- K0: init ---------------------------------------------------------
__global__ void k_init() {
    int i = blockIdx.x * blockDim.x + threadIdx.x;
    if (i < NN) { g_deg[i] = 1.0f; g_cnt[i] = 0; }
}

// ---------- K1 (fat): gemm1 (fp32+fp16 out) | extract+count ------------------
__global__ void k_fat1(const float* __restrict__ x, const float* __restrict__ W1,
                       const void* __restrict__ ei, const float* __restrict__ w) {
    __shared__ float sW[16 * 64];
    __shared__ float sxT[16 * 264];

    int tid = threadIdx.x;

    if (blockIdx.x < GB1) {
        int rowbase = blockIdx.x * 256;
        int tx = tid & 7;
        int ty = tid >> 3;

        float acc[8][8];
        #pragma unroll
        for (int i = 0; i < 8; i++)
            #pragma unroll
            for (int j = 0; j < 8; j++) acc[i][j] = 0.f;

        for (int kc = 0; kc < 16; kc++) {
            __syncthreads();
            #pragma unroll
            for (int i = tid; i < 1024; i += 256)
                sW[i] = W1[(kc * 16 + (i >> 6)) * 64 + (i & 63)];
            #pragma unroll
            for (int i = tid; i < 1024; i += 256) {
                int r = i >> 2, kq = (i & 3) * 4;
                int row = rowbase + r;
                float4 v = (row < NN) ? *(const float4*)&x[row * FIN + kc * 16 + kq]
                                      : make_float4(0.f, 0.f, 0.f, 0.f);
                sxT[(kq + 0) * 264 + r] = v.x;
                sxT[(kq + 1) * 264 + r] = v.y;
                sxT[(kq + 2) * 264 + r] = v.z;
                sxT[(kq + 3) * 264 + r] = v.w;
            }
            __syncthreads();
            #pragma unroll
            for (int k = 0; k < 16; k++) {
                float xr[8], wn[8];
                *(float4*)&xr[0] = *(const float4*)&sxT[k * 264 + ty * 8];
                *(float4*)&xr[4] = *(const float4*)&sxT[k * 264 + ty * 8 + 4];
                *(float4*)&wn[0] = *(const float4*)&sW[k * 64 + tx * 8];
                *(float4*)&wn[4] = *(const float4*)&sW[k * 64 + tx * 8 + 4];
                #pragma unroll
                for (int i = 0; i < 8; i++)
                    #pragma unroll
                    for (int j = 0; j < 8; j++)
                        acc[i][j] += xr[i] * wn[j];
            }
        }
        #pragma unroll
        for (int i = 0; i < 8; i++) {
            int row = rowbase + ty * 8 + i;
            if (row < NN) {
                *(float4*)&g_H1[row * HD + tx * 8]     = make_float4(acc[i][0], acc[i][1], acc[i][2], acc[i][3]);
                *(float4*)&g_H1[row * HD + tx * 8 + 4] = make_float4(acc[i][4], acc[i][5], acc[i][6], acc[i][7]);
                __half2 hp[4];
                hp[0] = __floats2half2_rn(acc[i][0], acc[i][1]);
                hp[1] = __floats2half2_rn(acc[i][2], acc[i][3]);
                hp[2] = __floats2half2_rn(acc[i][4], acc[i][5]);
                hp[3] = __floats2half2_rn(acc[i][6], acc[i][7]);
                *(uint4*)&g_H1h[row * HD + tx * 8] = *(const uint4*)&hp[0];
            }
        }
    } else {
        int base = (blockIdx.x - GB1) * 1024;
        const long long* p64 = (const long long*)ei;
        const int*       p32 = (const int*)ei;

        long long v = p64[base + tid];
        int bad = (v < 0 || v >= NN) ? 1 : 0;
        int is64 = !__syncthreads_or(bad);

        #pragma unroll
        for (int i = 0; i < 4; i++) {
            int e = base + i * 256 + tid;
            if (e < EE) {
                int s, d;
                if (is64) { s = (int)p64[e]; d = (int)p64[EE + e]; }
                else      { s = p32[e];      d = p32[EE + e]; }
                g_src[e] = s; g_dst[e] = d;
                atomicAdd(&g_cnt[d], 1);
                atomicAdd(&g_deg[d], w[e]);
            }
        }
    }
}

// ---------- K2 (fat): scan1 | dinv + cur=0 -----------------------------------
__global__ void k_fat2() {
    int b = blockIdx.x, t = threadIdx.x;
    if (b < NB) {
        __shared__ int s[1024];
        int i = b * 1024 + t;
        int v = (i < NN) ? g_cnt[i] : 0;
        s[t] = v; __syncthreads();
        for (int off = 1; off < 1024; off <<= 1) {
            int add = (t >= off) ? s[t - off] : 0;
            __syncthreads();
            s[t] += add;
            __syncthreads();
        }
        if (i < NN) g_rowptr[i + 1] = s[t];
        if (t == 1023) g_bsum[b] = s[t];
    } else {
        int i = (b - NB) * 1024 + t;
        if (i < NN) {
            float d = g_deg[i];
            g_deg[i] = (d > 0.f) ? rsqrtf(d) : 0.f;
            g_cur[i] = 0;
        }
    }
}

// ---------- K3/K4: scan finish -----------------------------------------------
__global__ void k_scan2() {
    __shared__ int s[128];
    int t = threadIdx.x;
    int v = (t < NB) ? g_bsum[t] : 0;
    s[t] = v; __syncthreads();
    for (int off = 1; off < 128; off <<= 1) {
        int add = (t >= off) ? s[t - off] : 0;
        __syncthreads();
        s[t] += add;
        __syncthreads();
    }
    if (t < NB) g_bsum[t] = s[t];
}
__global__ void k_scan3() {
    int b = blockIdx.x, t = threadIdx.x;
    int i = b * 1024 + t;
    if (b > 0 && i < NN) g_rowptr[i + 1] += g_bsum[b - 1];
    if (b == 0 && t == 0) g_rowptr[0] = 0;
}

// ---------- K5: fill CSR (packed src+norm) -----------------------------------
__global__ void k_fill(const float* __restrict__ w) {
    int e = blockIdx.x * blockDim.x + threadIdx.x;
    if (e < EE) {
        int s = g_src[e];
        int d = g_dst[e];
        float nrm = g_deg[s] * w[e] * g_deg[d];
        int p = atomicAdd(&g_cur[d], 1);
        g_csr_sn[g_rowptr[d] + p] = make_int2(s, __float_as_int(nrm));
    }
}

// ---------- helper: accumulate 4 fp16 feats * nrm ----------------------------
__device__ __forceinline__ void acc_h4(float4& acc, const __half* basep, int idx, float nrm) {
    const __half2* p = (const __half2*)(basep + idx);
    __half2 r0 = p[0];
    __half2 r1 = p[1];
    float2 f0 = __half22float2(r0);
    float2 f1 = __half22float2(r1);
    acc.x += f0.x * nrm; acc.y += f0.y * nrm;
    acc.z += f1.x * nrm; acc.w += f1.y * nrm;
}

// ---------- K6: agg1 (fp16 gather) + self + bias + relu ----------------------
// 16 threads/node, 4 feats each, 4-wide unroll.
__global__ void k_agg1(const float* __restrict__ b1) {
    int tid = threadIdx.x;
    int v  = blockIdx.x * 16 + (tid >> 4);
    if (v >= NN) return;
    int c4 = (tid & 15) * 4;

    int e   = g_rowptr[v];
    int end = g_rowptr[v + 1];
    float4 acc = make_float4(0.f, 0.f, 0.f, 0.f);

    for (; e + 4 <= end; e += 4) {
        int2 sn0 = g_csr_sn[e],     sn1 = g_csr_sn[e + 1];
        int2 sn2 = g_csr_sn[e + 2], sn3 = g_csr_sn[e + 3];
        acc_h4(acc, g_H1h, sn0.x * HD + c4, __int_as_float(sn0.y));
        acc_h4(acc, g_H1h, sn1.x * HD + c4, __int_as_float(sn1.y));
        acc_h4(acc, g_H1h, sn2.x * HD + c4, __int_as_float(sn2.y));
        acc_h4(acc, g_H1h, sn3.x * HD + c4, __int_as_float(sn3.y));
    }
    for (; e < end; e++) {
        int2 sn = g_csr_sn[e];
        acc_h4(acc, g_H1h, sn.x * HD + c4, __int_as_float(sn.y));
    }

    float di = g_deg[v];
    float sn2 = di * di;
    float4 hs = *(const float4*)&g_H1[v * HD + c4];
    float4 bb = *(const float4*)&b1[c4];
    float4 o;
    o.x = fmaxf(acc.x + hs.x * sn2 + bb.x, 0.f);
    o.y = fmaxf(acc.y + hs.y * sn2 + bb.y, 0.f);
    o.z = fmaxf(acc.z + hs.z * sn2 + bb.z, 0.f);
    o.w = fmaxf(acc.w + hs.w * sn2 + bb.w, 0.f);
    *(float4*)&g_H1b[v * HD + c4] = o;
}

// ---------- K7: GEMM2 (row x 4col per thread; fp32 + fp16 out) ---------------
__global__ void k_gemm2(const float* __restrict__ W2) {
    __shared__ float sW2[64 * 40];
    __shared__ float sx[32 * 64];

    int tid = threadIdx.x;
    int rowbase = blockIdx.x * 32;

    for (int idx = tid; idx < 64 * 40; idx += 320)
        sW2[idx] = W2[idx];
    for (int idx = tid; idx < 32 * 64; idx += 320) {
        int r = idx >> 6, k = idx & 63;
        int row = rowbase + r;
        sx[idx] = (row < NN) ? g_H1b[row * HD + k] : 0.f;
    }
    __syncthreads();

    int cg = tid % 10;          // col group: cols 4*cg..4*cg+3
    int r  = tid / 10;          // local row 0..31
    int row = rowbase + r;

    float4 a = make_float4(0.f, 0.f, 0.f, 0.f);
    #pragma unroll
    for (int k = 0; k < 64; k++) {
        float xv = sx[r * 64 + k];
        float4 wv = *(const float4*)&sW2[k * 40 + cg * 4];
        a.x += xv * wv.x; a.y += xv * wv.y;
        a.z += xv * wv.z; a.w += xv * wv.w;
    }
    if (row < NN) {
        *(float4*)&g_H2[row * CD + cg * 4] = a;
        __half2 hp[2];
        hp[0] = __floats2half2_rn(a.x, a.y);
        hp[1] = __floats2half2_rn(a.z, a.w);
        *(uint2*)&g_H2h[row * CD + cg * 4] = *(const uint2*)&hp[0];
    }
}

// ---------- K8: agg2 (fp16 gather) + self + bias + log_softmax ---------------
__global__ void k_agg2(const float* __restrict__ b2, float* __restrict__ out) {
    __shared__ float sp[32 * 10];
    __shared__ float sm[32];
    __shared__ float sl[32];

    int tid = threadIdx.x;
    int nl = tid / 10;
    int j  = tid % 10;
    int v  = blockIdx.x * 32 + nl;
    bool act = (v < NN);
    int c4 = j * 4;

    float4 acc = make_float4(0.f, 0.f, 0.f, 0.f);
    if (act) {
        int e   = g_rowptr[v];
        int end = g_rowptr[v + 1];
        for (; e + 4 <= end; e += 4) {
            int2 sn0 = g_csr_sn[e],     sn1 = g_csr_sn[e + 1];
            int2 sn2 = g_csr_sn[e + 2], sn3 = g_csr_sn[e + 3];
            acc_h4(acc, g_H2h, sn0.x * CD + c4, __int_as_float(sn0.y));
            acc_h4(acc, g_H2h, sn1.x * CD + c4, __int_as_float(sn1.y));
            acc_h4(acc, g_H2h, sn2.x * CD + c4, __int_as_float(sn2.y));
            acc_h4(acc, g_H2h, sn3.x * CD + c4, __int_as_float(sn3.y));
        }
        for (; e < end; e++) {
            int2 sn = g_csr_sn[e];
            acc_h4(acc, g_H2h, sn.x * CD + c4, __int_as_float(sn.y));
        }
        float di = g_deg[v];
        float sn2 = di * di;
        float4 hs = *(const float4*)&g_H2[v * CD + c4];
        float4 bb = *(const float4*)&b2[c4];
        acc.x += hs.x * sn2 + bb.x;
        acc.y += hs.y * sn2 + bb.y;
        acc.z += hs.z * sn2 + bb.z;
        acc.w += hs.w * sn2 + bb.w;
    }

    float pm = fmaxf(fmaxf(acc.x, acc.y), fmaxf(acc.z, acc.w));
    sp[nl * 10 + j] = act ? pm : -FLT_MAX;
    __syncthreads();
    if (j == 0) {
        float m = sp[nl * 10];
        #pragma unroll
        for (int t = 1; t < 10; t++) m = fmaxf(m, sp[nl * 10 + t]);
        sm[nl] = m;
    }
    __syncthreads();
    float m = sm[nl];
    float ps = act ? (__expf(acc.x - m) + __expf(acc.y - m) + __expf(acc.z - m) + __expf(acc.w - m)) : 0.f;
    sp[nl * 10 + j] = ps;
    __syncthreads();
    if (j == 0) {
        float s = 0.f;
        #pragma unroll
        for (int t = 0; t < 10; t++) s += sp[nl * 10 + t];
        sl[nl] = m + __logf(s);
    }
    __syncthreads();
    if (act) {
        float ls = sl[nl];
        int base = v * CD + c4;
        out[base + 0] = acc.x - ls;
        out[base + 1] = acc.y - ls;
        out[base + 2] = acc.z - ls;
        out[base + 3] = acc.w - ls;
    }
}

extern "C" void kernel_launch(void* const* d_in, const int* in_sizes, int n_in,
                              void* d_out, int out_size) {
    const float* x   = (const float*)d_in[0];
    const void*  ei  = d_in[1];
    const float* ea  = (const float*)d_in[2];
    const float* W1  = (const float*)d_in[3];
    const float* b1  = (const float*)d_in[4];
    const float* W2  = (const float*)d_in[5];
    const float* b2  = (const float*)d_in[6];
    float*       out = (float*)d_out;

    k_init <<<(NN + 255) / 256, 256>>>();
    k_fat1 <<<GB1 + EB1, 256>>>(x, W1, ei, ea);
    k_fat2 <<<2 * NB, 1024>>>();
    k_scan2<<<1, 128>>>();
    k_scan3<<<NB, 1024>>>();
    k_fill <<<(EE + 255) / 256, 256>>>(ea);
    k_agg1 <<<(NN + 15) / 16, 256>>>(b1);
    k_gemm2<<<(NN + 31) / 32, 320>>>(W2);
    k_agg2 <<<(NN + 31) / 32, 320>>>(b2, out);
}

// round 15
// speedup vs baseline: 1.0113x; 1.0113x over previous
#include <cuda_runtime.h>
#include <cuda_fp16.h>
#include <math.h>
#include <float.h>

#define NN 100000
#define EE 1600000
#define FIN 256
#define HD 64
#define CD 40
#define NB 98                 // ceil(NN/1024) scan blocks
#define GB1 391               // gemm1 blocks: ceil(NN/256)
#define EB1 1563              // extract blocks: ceil(EE/1024)

// ---- scratch ----------------------------------------------------------------
__device__ __align__(16) float g_deg[NN];         // deg -> dinv in place
__device__ __align__(16) float g_H1[NN * HD];     // x@W1 fp32
__device__ __align__(16) float g_H1b[NN * HD];    // relu(agg1)
__device__ __align__(16) float g_H2[NN * CD];     // h1b@W2
__device__ int   g_src[EE];
__device__ int   g_dst[EE];
__device__ int   g_cnt[NN];
__device__ int   g_cur[NN];
__device__ int   g_rowptr[NN + 1];
__device__ int   g_bsum[128];
__device__ __align__(16) int2 g_csr_sn[EE];       // (src, norm-bits) in CSR order

// ---------- K0: init ---------------------------------------------------------
__global__ void k_init() {
    int i = blockIdx.x * blockDim.x + threadIdx.x;
    if (i < NN) { g_deg[i] = 1.0f; g_cnt[i] = 0; }
}

// ---------- K1 (fat): gemm1 | extract+count ----------------------------------
__global__ void k_fat1(const float* __restrict__ x, const float* __restrict__ W1,
                       const void* __restrict__ ei, const float* __restrict__ w) {
    __shared__ float sW[16 * 64];
    __shared__ float sxT[16 * 264];

    int tid = threadIdx.x;

    if (blockIdx.x < GB1) {
        int rowbase = blockIdx.x * 256;
        int tx = tid & 7;
        int ty = tid >> 3;

        float acc[8][8];
        #pragma unroll
        for (int i = 0; i < 8; i++)
            #pragma unroll
            for (int j = 0; j < 8; j++) acc[i][j] = 0.f;

        for (int kc = 0; kc < 16; kc++) {
            __syncthreads();
            #pragma unroll
            for (int i = tid; i < 1024; i += 256)
                sW[i] = W1[(kc * 16 + (i >> 6)) * 64 + (i & 63)];
            #pragma unroll
            for (int i = tid; i < 1024; i += 256) {
                int r = i >> 2, kq = (i & 3) * 4;
                int row = rowbase + r;
                float4 v = (row < NN) ? *(const float4*)&x[row * FIN + kc * 16 + kq]
                                      : make_float4(0.f, 0.f, 0.f, 0.f);
                sxT[(kq + 0) * 264 + r] = v.x;
                sxT[(kq + 1) * 264 + r] = v.y;
                sxT[(kq + 2) * 264 + r] = v.z;
                sxT[(kq + 3) * 264 + r] = v.w;
            }
            __syncthreads();
            #pragma unroll
            for (int k = 0; k < 16; k++) {
                float xr[8], wn[8];
                *(float4*)&xr[0] = *(const float4*)&sxT[k * 264 + ty * 8];
                *(float4*)&xr[4] = *(const float4*)&sxT[k * 264 + ty * 8 + 4];
                *(float4*)&wn[0] = *(const float4*)&sW[k * 64 + tx * 8];
                *(float4*)&wn[4] = *(const float4*)&sW[k * 64 + tx * 8 + 4];
                #pragma unroll
                for (int i = 0; i < 8; i++)
                    #pragma unroll
                    for (int j = 0; j < 8; j++)
                        acc[i][j] += xr[i] * wn[j];
            }
        }
        #pragma unroll
        for (int i = 0; i < 8; i++) {
            int row = rowbase + ty * 8 + i;
            if (row < NN) {
                *(float4*)&g_H1[row * HD + tx * 8]     = make_float4(acc[i][0], acc[i][1], acc[i][2], acc[i][3]);
                *(float4*)&g_H1[row * HD + tx * 8 + 4] = make_float4(acc[i][4], acc[i][5], acc[i][6], acc[i][7]);
            }
        }
    } else {
        int base = (blockIdx.x - GB1) * 1024;
        const long long* p64 = (const long long*)ei;
        const int*       p32 = (const int*)ei;

        long long v = p64[base + tid];
        int bad = (v < 0 || v >= NN) ? 1 : 0;
        int is64 = !__syncthreads_or(bad);

        #pragma unroll
        for (int i = 0; i < 4; i++) {
            int e = base + i * 256 + tid;
            if (e < EE) {
                int s, d;
                if (is64) { s = (int)p64[e]; d = (int)p64[EE + e]; }
                else      { s = p32[e];      d = p32[EE + e]; }
                g_src[e] = s; g_dst[e] = d;
                atomicAdd(&g_cnt[d], 1);
                atomicAdd(&g_deg[d], w[e]);
            }
        }
    }
}

// ---------- K2 (fat): scan1 | dinv + cur=0 -----------------------------------
__global__ void k_fat2() {
    int b = blockIdx.x, t = threadIdx.x;
    if (b < NB) {
        __shared__ int s[1024];
        int i = b * 1024 + t;
        int v = (i < NN) ? g_cnt[i] : 0;
        s[t] = v; __syncthreads();
        for (int off = 1; off < 1024; off <<= 1) {
            int add = (t >= off) ? s[t - off] : 0;
            __syncthreads();
            s[t] += add;
            __syncthreads();
        }
        if (i < NN) g_rowptr[i + 1] = s[t];
        if (t == 1023) g_bsum[b] = s[t];
    } else {
        int i = (b - NB) * 1024 + t;
        if (i < NN) {
            float d = g_deg[i];
            g_deg[i] = (d > 0.f) ? rsqrtf(d) : 0.f;
            g_cur[i] = 0;
        }
    }
}

// ---------- K3/K4: scan finish -----------------------------------------------
__global__ void k_scan2() {
    __shared__ int s[128];
    int t = threadIdx.x;
    int v = (t < NB) ? g_bsum[t] : 0;
    s[t] = v; __syncthreads();
    for (int off = 1; off < 128; off <<= 1) {
        int add = (t >= off) ? s[t - off] : 0;
        __syncthreads();
        s[t] += add;
        __syncthreads();
    }
    if (t < NB) g_bsum[t] = s[t];
}
__global__ void k_scan3() {
    int b = blockIdx.x, t = threadIdx.x;
    int i = b * 1024 + t;
    if (b > 0 && i < NN) g_rowptr[i + 1] += g_bsum[b - 1];
    if (b == 0 && t == 0) g_rowptr[0] = 0;
}

// ---------- K5: fill CSR (packed src+norm) -----------------------------------
__global__ void k_fill(const float* __restrict__ w) {
    int e = blockIdx.x * blockDim.x + threadIdx.x;
    if (e < EE) {
        int s = g_src[e];
        int d = g_dst[e];
        float nrm = g_deg[s] * w[e] * g_deg[d];
        int p = atomicAdd(&g_cur[d], 1);
        g_csr_sn[g_rowptr[d] + p] = make_int2(s, __float_as_int(nrm));
    }
}

// ---------- K6: agg1 — warp per node, 2 edges/iter, x2 pipeline --------------
// lanes 0-15: edge e (+half=0), lanes 16-31: edge e+1 (half=1);
// each lane covers 4 features (c4 = (lane&15)*4). Final cross-half SHFL combine.
__global__ void k_agg1(const float* __restrict__ b1) {
    int v = (blockIdx.x * blockDim.x + threadIdx.x) >> 5;
    if (v >= NN) return;
    int lane = threadIdx.x & 31;
    int half = lane >> 4;
    int c4 = (lane & 15) * 4;

    int e   = g_rowptr[v];
    int end = g_rowptr[v + 1];
    float4 acc = make_float4(0.f, 0.f, 0.f, 0.f);

    // 4 edges per iteration (2 per half-warp)
    for (; e + 4 <= end; e += 4) {
        int2 sna = g_csr_sn[e + half];
        int2 snb = g_csr_sn[e + 2 + half];
        float na = __int_as_float(sna.y);
        float nb = __int_as_float(snb.y);
        float4 ha = *(const float4*)&g_H1[sna.x * HD + c4];
        float4 hb = *(const float4*)&g_H1[snb.x * HD + c4];
        acc.x += ha.x * na + hb.x * nb;
        acc.y += ha.y * na + hb.y * nb;
        acc.z += ha.z * na + hb.z * nb;
        acc.w += ha.w * na + hb.w * nb;
    }
    if (e + 2 <= end) {
        int2 sn = g_csr_sn[e + half];
        float n = __int_as_float(sn.y);
        float4 h = *(const float4*)&g_H1[sn.x * HD + c4];
        acc.x += h.x * n; acc.y += h.y * n;
        acc.z += h.z * n; acc.w += h.w * n;
        e += 2;
    }
    if (e < end && half == 0) {
        int2 sn = g_csr_sn[e];
        float n = __int_as_float(sn.y);
        float4 h = *(const float4*)&g_H1[sn.x * HD + c4];
        acc.x += h.x * n; acc.y += h.y * n;
        acc.z += h.z * n; acc.w += h.w * n;
    }

    // combine halves: lane i += lane i+16
    acc.x += __shfl_xor_sync(0xFFFFFFFFu, acc.x, 16);
    acc.y += __shfl_xor_sync(0xFFFFFFFFu, acc.y, 16);
    acc.z += __shfl_xor_sync(0xFFFFFFFFu, acc.z, 16);
    acc.w += __shfl_xor_sync(0xFFFFFFFFu, acc.w, 16);

    if (half == 0) {
        float di = g_deg[v];
        float sn2 = di * di;
        float4 hs = *(const float4*)&g_H1[v * HD + c4];
        float4 bb = *(const float4*)&b1[c4];
        float4 o;
        o.x = fmaxf(acc.x + hs.x * sn2 + bb.x, 0.f);
        o.y = fmaxf(acc.y + hs.y * sn2 + bb.y, 0.f);
        o.z = fmaxf(acc.z + hs.z * sn2 + bb.z, 0.f);
        o.w = fmaxf(acc.w + hs.w * sn2 + bb.w, 0.f);
        *(float4*)&g_H1b[v * HD + c4] = o;
    }
}

// ---------- K7: GEMM2 (row x 4col per thread) --------------------------------
__global__ void k_gemm2(const float* __restrict__ W2) {
    __shared__ float sW2[64 * 40];
    __shared__ float sx[32 * 64];

    int tid = threadIdx.x;
    int rowbase = blockIdx.x * 32;

    for (int idx = tid; idx < 64 * 40; idx += 320)
        sW2[idx] = W2[idx];
    for (int idx = tid; idx < 32 * 64; idx += 320) {
        int r = idx >> 6, k = idx & 63;
        int row = rowbase + r;
        sx[idx] = (row < NN) ? g_H1b[row * HD + k] : 0.f;
    }
    __syncthreads();

    int cg = tid % 10;
    int r  = tid / 10;
    int row = rowbase + r;

    float4 a = make_float4(0.f, 0.f, 0.f, 0.f);
    #pragma unroll
    for (int k = 0; k < 64; k++) {
        float xv = sx[r * 64 + k];
        float4 wv = *(const float4*)&sW2[k * 40 + cg * 4];
        a.x += xv * wv.x; a.y += xv * wv.y;
        a.z += xv * wv.z; a.w += xv * wv.w;
    }
    if (row < NN) *(float4*)&g_H2[row * CD + cg * 4] = a;
}

// ---------- K8: agg2 (fp32 gather) + self + bias + log_softmax ---------------
__global__ void k_agg2(const float* __restrict__ b2, float* __restrict__ out) {
    __shared__ float sp[32 * 10];
    __shared__ float sm[32];
    __shared__ float sl[32];

    int tid = threadIdx.x;
    int nl = tid / 10;
    int j  = tid % 10;
    int v  = blockIdx.x * 32 + nl;
    bool act = (v < NN);
    int c4 = j * 4;

    float4 acc = make_float4(0.f, 0.f, 0.f, 0.f);
    if (act) {
        int e   = g_rowptr[v];
        int end = g_rowptr[v + 1];
        for (; e + 4 <= end; e += 4) {
            int2 sn0 = g_csr_sn[e],     sn1 = g_csr_sn[e + 1];
            int2 sn2 = g_csr_sn[e + 2], sn3 = g_csr_sn[e + 3];
            float4 h0 = *(const float4*)&g_H2[sn0.x * CD + c4];
            float4 h1 = *(const float4*)&g_H2[sn1.x * CD + c4];
            float4 h2 = *(const float4*)&g_H2[sn2.x * CD + c4];
            float4 h3 = *(const float4*)&g_H2[sn3.x * CD + c4];
            float n0 = __int_as_float(sn0.y), n1 = __int_as_float(sn1.y);
            float n2 = __int_as_float(sn2.y), n3 = __int_as_float(sn3.y);
            acc.x += h0.x * n0 + h1.x * n1 + h2.x * n2 + h3.x * n3;
            acc.y += h0.y * n0 + h1.y * n1 + h2.y * n2 + h3.y * n3;
            acc.z += h0.z * n0 + h1.z * n1 + h2.z * n2 + h3.z * n3;
            acc.w += h0.w * n0 + h1.w * n1 + h2.w * n2 + h3.w * n3;
        }
        for (; e < end; e++) {
            int2 sn = g_csr_sn[e];
            float n = __int_as_float(sn.y);
            float4 h = *(const float4*)&g_H2[sn.x * CD + c4];
            acc.x += h.x * n; acc.y += h.y * n;
            acc.z += h.z * n; acc.w += h.w * n;
        }
        float di = g_deg[v];
        float sn2 = di * di;
        float4 hs = *(const float4*)&g_H2[v * CD + c4];
        float4 bb = *(const float4*)&b2[c4];
        acc.x += hs.x * sn2 + bb.x;
        acc.y += hs.y * sn2 + bb.y;
        acc.z += hs.z * sn2 + bb.z;
        acc.w += hs.w * sn2 + bb.w;
    }

    float pm = fmaxf(fmaxf(acc.x, acc.y), fmaxf(acc.z, acc.w));
    sp[nl * 10 + j] = act ? pm : -FLT_MAX;
    __syncthreads();
    if (j == 0) {
        float m = sp[nl * 10];
        #pragma unroll
        for (int t = 1; t < 10; t++) m = fmaxf(m, sp[nl * 10 + t]);
        sm[nl] = m;
    }
    __syncthreads();
    float m = sm[nl];
    float ps = act ? (__expf(acc.x - m) + __expf(acc.y - m) + __expf(acc.z - m) + __expf(acc.w - m)) : 0.f;
    sp[nl * 10 + j] = ps;
    __syncthreads();
    if (j == 0) {
        float s = 0.f;
        #pragma unroll
        for (int t = 0; t < 10; t++) s += sp[nl * 10 + t];
        sl[nl] = m + __logf(s);
    }
    __syncthreads();
    if (act) {
        float ls = sl[nl];
        int base = v * CD + c4;
        out[base + 0] = acc.x - ls;
        out[base + 1] = acc.y - ls;
        out[base + 2] = acc.z - ls;
        out[base + 3] = acc.w - ls;
    }
}

extern "C" void kernel_launch(void* const* d_in, const int* in_sizes, int n_in,
                              void* d_out, int out_size) {
    const float* x   = (const float*)d_in[0];
    const void*  ei  = d_in[1];
    const float* ea  = (const float*)d_in[2];
    const float* W1  = (const float*)d_in[3];
    const float* b1  = (const float*)d_in[4];
    const float* W2  = (const float*)d_in[5];
    const float* b2  = (const float*)d_in[6];
    float*       out = (float*)d_out;

    k_init <<<(NN + 255) / 256, 256>>>();
    k_fat1 <<<GB1 + EB1, 256>>>(x, W1, ei, ea);
    k_fat2 <<<2 * NB, 1024>>>();
    k_scan2<<<1, 128>>>();
    k_scan3<<<NB, 1024>>>();
    k_fill <<<(EE + 255) / 256, 256>>>(ea);
    k_agg1 <<<(NN * 32 + 255) / 256, 256>>>(b1);
    k_gemm2<<<(NN + 31) / 32, 320>>>(W2);
    k_agg2 <<<(NN + 31) / 32, 320>>>(b2, out);
}

// round 16
// speedup vs baseline: 1.0524x; 1.0407x over previous
#include <cuda_runtime.h>
#include <math.h>
#include <float.h>

#define NN 100000
#define EE 1600000
#define FIN 256
#define HD 64
#define CD 40
#define NB 98                 // ceil(NN/1024) scan blocks
#define GB1 391               // gemm1 blocks: ceil(NN/256)
#define EB1 1563              // extract blocks: ceil(EE/1024)

// ---- scratch ----------------------------------------------------------------
__device__ __align__(16) float g_deg[NN];         // deg -> dinv in place
__device__ __align__(16) float g_H1[NN * HD];     // x@W1 fp32
__device__ __align__(16) float g_H2[NN * CD];     // (relu(agg1)) @ W2
__device__ int   g_src[EE];
__device__ int   g_dst[EE];
__device__ int   g_cnt[NN];
__device__ int   g_cur[NN];
__device__ int   g_rowptr[NN + 1];
__device__ int   g_bsum[128];
__device__ __align__(16) int2 g_csr_sn[EE];       // (src, norm-bits) in CSR order

// ---------- K0: init ---------------------------------------------------------
__global__ void k_init() {
    int i = blockIdx.x * blockDim.x + threadIdx.x;
    if (i < NN) { g_deg[i] = 1.0f; g_cnt[i] = 0; }
}

// ---------- K1 (fat): gemm1 | extract+count ----------------------------------
__global__ void k_fat1(const float* __restrict__ x, const float* __restrict__ W1,
                       const void* __restrict__ ei, const float* __restrict__ w) {
    __shared__ float sW[16 * 64];
    __shared__ float sxT[16 * 264];

    int tid = threadIdx.x;

    if (blockIdx.x < GB1) {
        int rowbase = blockIdx.x * 256;
        int tx = tid & 7;
        int ty = tid >> 3;

        float acc[8][8];
        #pragma unroll
        for (int i = 0; i < 8; i++)
            #pragma unroll
            for (int j = 0; j < 8; j++) acc[i][j] = 0.f;

        for (int kc = 0; kc < 16; kc++) {
            __syncthreads();
            #pragma unroll
            for (int i = tid; i < 1024; i += 256)
                sW[i] = W1[(kc * 16 + (i >> 6)) * 64 + (i & 63)];
            #pragma unroll
            for (int i = tid; i < 1024; i += 256) {
                int r = i >> 2, kq = (i & 3) * 4;
                int row = rowbase + r;
                float4 v = (row < NN) ? *(const float4*)&x[row * FIN + kc * 16 + kq]
                                      : make_float4(0.f, 0.f, 0.f, 0.f);
                sxT[(kq + 0) * 264 + r] = v.x;
                sxT[(kq + 1) * 264 + r] = v.y;
                sxT[(kq + 2) * 264 + r] = v.z;
                sxT[(kq + 3) * 264 + r] = v.w;
            }
            __syncthreads();
            #pragma unroll
            for (int k = 0; k < 16; k++) {
                float xr[8], wn[8];
                *(float4*)&xr[0] = *(const float4*)&sxT[k * 264 + ty * 8];
                *(float4*)&xr[4] = *(const float4*)&sxT[k * 264 + ty * 8 + 4];
                *(float4*)&wn[0] = *(const float4*)&sW[k * 64 + tx * 8];
                *(float4*)&wn[4] = *(const float4*)&sW[k * 64 + tx * 8 + 4];
                #pragma unroll
                for (int i = 0; i < 8; i++)
                    #pragma unroll
                    for (int j = 0; j < 8; j++)
                        acc[i][j] += xr[i] * wn[j];
            }
        }
        #pragma unroll
        for (int i = 0; i < 8; i++) {
            int row = rowbase + ty * 8 + i;
            if (row < NN) {
                *(float4*)&g_H1[row * HD + tx * 8]     = make_float4(acc[i][0], acc[i][1], acc[i][2], acc[i][3]);
                *(float4*)&g_H1[row * HD + tx * 8 + 4] = make_float4(acc[i][4], acc[i][5], acc[i][6], acc[i][7]);
            }
        }
    } else {
        int base = (blockIdx.x - GB1) * 1024;
        const long long* p64 = (const long long*)ei;
        const int*       p32 = (const int*)ei;

        long long v = p64[base + tid];
        int bad = (v < 0 || v >= NN) ? 1 : 0;
        int is64 = !__syncthreads_or(bad);

        #pragma unroll
        for (int i = 0; i < 4; i++) {
            int e = base + i * 256 + tid;
            if (e < EE) {
                int s, d;
                if (is64) { s = (int)p64[e]; d = (int)p64[EE + e]; }
                else      { s = p32[e];      d = p32[EE + e]; }
                g_src[e] = s; g_dst[e] = d;
                atomicAdd(&g_cnt[d], 1);
                atomicAdd(&g_deg[d], w[e]);
            }
        }
    }
}

// ---------- K2 (fat): scan1 | dinv + cur=0 -----------------------------------
__global__ void k_fat2() {
    int b = blockIdx.x, t = threadIdx.x;
    if (b < NB) {
        __shared__ int s[1024];
        int i = b * 1024 + t;
        int v = (i < NN) ? g_cnt[i] : 0;
        s[t] = v; __syncthreads();
        for (int off = 1; off < 1024; off <<= 1) {
            int add = (t >= off) ? s[t - off] : 0;
            __syncthreads();
            s[t] += add;
            __syncthreads();
        }
        if (i < NN) g_rowptr[i + 1] = s[t];
        if (t == 1023) g_bsum[b] = s[t];
    } else {
        int i = (b - NB) * 1024 + t;
        if (i < NN) {
            float d = g_deg[i];
            g_deg[i] = (d > 0.f) ? rsqrtf(d) : 0.f;
            g_cur[i] = 0;
        }
    }
}

// ---------- K3/K4: scan finish -----------------------------------------------
__global__ void k_scan2() {
    __shared__ int s[128];
    int t = threadIdx.x;
    int v = (t < NB) ? g_bsum[t] : 0;
    s[t] = v; __syncthreads();
    for (int off = 1; off < 128; off <<= 1) {
        int add = (t >= off) ? s[t - off] : 0;
        __syncthreads();
        s[t] += add;
        __syncthreads();
    }
    if (t < NB) g_bsum[t] = s[t];
}
__global__ void k_scan3() {
    int b = blockIdx.x, t = threadIdx.x;
    int i = b * 1024 + t;
    if (b > 0 && i < NN) g_rowptr[i + 1] += g_bsum[b - 1];
    if (b == 0 && t == 0) g_rowptr[0] = 0;
}

// ---------- K5: fill CSR (packed src+norm) -----------------------------------
__global__ void k_fill(const float* __restrict__ w) {
    int e = blockIdx.x * blockDim.x + threadIdx.x;
    if (e < EE) {
        int s = g_src[e];
        int d = g_dst[e];
        float nrm = g_deg[s] * w[e] * g_deg[d];
        int p = atomicAdd(&g_cur[d], 1);
        g_csr_sn[g_rowptr[d] + p] = make_int2(s, __float_as_int(nrm));
    }
}

// ---------- K6: agg1 + relu + GEMM2, fused -----------------------------------
// 512 threads = 32 nodes x 16 lanes. Phase 1: CSR gather agg -> smem (R9 map).
// Phase 2: 320 threads compute H2 = relu(H1b) @ W2 from smem.
__global__ void k_agg1g2(const float* __restrict__ b1, const float* __restrict__ W2) {
    __shared__ float sH[32 * 68];     // relu'd H1b tile, padded (68 mod 32 = 4)
    __shared__ float sW2[64 * 40];

    int tid = threadIdx.x;
    int nl  = tid >> 4;               // node local 0..31
    int c4  = (tid & 15) * 4;         // feature quad
    int v   = blockIdx.x * 32 + nl;

    // cooperative W2 load (2560 floats / 512 threads = 5 each)
    #pragma unroll
    for (int i = tid; i < 64 * 40; i += 512)
        sW2[i] = W2[i];

    if (v < NN) {
        int e   = g_rowptr[v];
        int end = g_rowptr[v + 1];
        float4 acc = make_float4(0.f, 0.f, 0.f, 0.f);

        for (; e + 4 <= end; e += 4) {
            int2 sn0 = g_csr_sn[e],     sn1 = g_csr_sn[e + 1];
            int2 sn2 = g_csr_sn[e + 2], sn3 = g_csr_sn[e + 3];
            float4 h0 = *(const float4*)&g_H1[sn0.x * HD + c4];
            float4 h1 = *(const float4*)&g_H1[sn1.x * HD + c4];
            float4 h2 = *(const float4*)&g_H1[sn2.x * HD + c4];
            float4 h3 = *(const float4*)&g_H1[sn3.x * HD + c4];
            float n0 = __int_as_float(sn0.y), n1 = __int_as_float(sn1.y);
            float n2 = __int_as_float(sn2.y), n3 = __int_as_float(sn3.y);
            acc.x += h0.x * n0 + h1.x * n1 + h2.x * n2 + h3.x * n3;
            acc.y += h0.y * n0 + h1.y * n1 + h2.y * n2 + h3.y * n3;
            acc.z += h0.z * n0 + h1.z * n1 + h2.z * n2 + h3.z * n3;
            acc.w += h0.w * n0 + h1.w * n1 + h2.w * n2 + h3.w * n3;
        }
        for (; e < end; e++) {
            int2 sn = g_csr_sn[e];
            float n = __int_as_float(sn.y);
            float4 h = *(const float4*)&g_H1[sn.x * HD + c4];
            acc.x += h.x * n; acc.y += h.y * n;
            acc.z += h.z * n; acc.w += h.w * n;
        }

        float di = g_deg[v];
        float sn2 = di * di;
        float4 hs = *(const float4*)&g_H1[v * HD + c4];
        float4 bb = *(const float4*)&b1[c4];
        sH[nl * 68 + c4 + 0] = fmaxf(acc.x + hs.x * sn2 + bb.x, 0.f);
        sH[nl * 68 + c4 + 1] = fmaxf(acc.y + hs.y * sn2 + bb.y, 0.f);
        sH[nl * 68 + c4 + 2] = fmaxf(acc.z + hs.z * sn2 + bb.z, 0.f);
        sH[nl * 68 + c4 + 3] = fmaxf(acc.w + hs.w * sn2 + bb.w, 0.f);
    }
    __syncthreads();

    // phase 2: H2 tile = sH @ W2  (320 active threads: node x 4-col group)
    if (tid < 320) {
        int n2 = tid / 10;
        int cg = tid % 10;
        int vv = blockIdx.x * 32 + n2;
        if (vv < NN) {
            float4 a = make_float4(0.f, 0.f, 0.f, 0.f);
            const float* hrow = &sH[n2 * 68];
            #pragma unroll
            for (int k = 0; k < 64; k++) {
                float xv = hrow[k];
                float4 wv = *(const float4*)&sW2[k * 40 + cg * 4];
                a.x += xv * wv.x; a.y += xv * wv.y;
                a.z += xv * wv.z; a.w += xv * wv.w;
            }
            *(float4*)&g_H2[vv * CD + cg * 4] = a;
        }
    }
}

// ---------- K7: agg2 (fp32 gather) + self + bias + log_softmax ---------------
__global__ void k_agg2(const float* __restrict__ b2, float* __restrict__ out) {
    __shared__ float sp[32 * 10];
    __shared__ float sm[32];
    __shared__ float sl[32];

    int tid = threadIdx.x;
    int nl = tid / 10;
    int j  = tid % 10;
    int v  = blockIdx.x * 32 + nl;
    bool act = (v < NN);
    int c4 = j * 4;

    float4 acc = make_float4(0.f, 0.f, 0.f, 0.f);
    if (act) {
        int e   = g_rowptr[v];
        int end = g_rowptr[v + 1];
        for (; e + 4 <= end; e += 4) {
            int2 sn0 = g_csr_sn[e],     sn1 = g_csr_sn[e + 1];
            int2 sn2 = g_csr_sn[e + 2], sn3 = g_csr_sn[e + 3];
            float4 h0 = *(const float4*)&g_H2[sn0.x * CD + c4];
            float4 h1 = *(const float4*)&g_H2[sn1.x * CD + c4];
            float4 h2 = *(const float4*)&g_H2[sn2.x * CD + c4];
            float4 h3 = *(const float4*)&g_H2[sn3.x * CD + c4];
            float n0 = __int_as_float(sn0.y), n1 = __int_as_float(sn1.y);
            float n2 = __int_as_float(sn2.y), n3 = __int_as_float(sn3.y);
            acc.x += h0.x * n0 + h1.x * n1 + h2.x * n2 + h3.x * n3;
            acc.y += h0.y * n0 + h1.y * n1 + h2.y * n2 + h3.y * n3;
            acc.z += h0.z * n0 + h1.z * n1 + h2.z * n2 + h3.z * n3;
            acc.w += h0.w * n0 + h1.w * n1 + h2.w * n2 + h3.w * n3;
        }
        for (; e < end; e++) {
            int2 sn = g_csr_sn[e];
            float n = __int_as_float(sn.y);
            float4 h = *(const float4*)&g_H2[sn.x * CD + c4];
            acc.x += h.x * n; acc.y += h.y * n;
            acc.z += h.z * n; acc.w += h.w * n;
        }
        float di = g_deg[v];
        float sn2 = di * di;
        float4 hs = *(const float4*)&g_H2[v * CD + c4];
        float4 bb = *(const float4*)&b2[c4];
        acc.x += hs.x * sn2 + bb.x;
        acc.y += hs.y * sn2 + bb.y;
        acc.z += hs.z * sn2 + bb.z;
        acc.w += hs.w * sn2 + bb.w;
    }

    float pm = fmaxf(fmaxf(acc.x, acc.y), fmaxf(acc.z, acc.w));
    sp[nl * 10 + j] = act ? pm : -FLT_MAX;
    __syncthreads();
    if (j == 0) {
        float m = sp[nl * 10];
        #pragma unroll
        for (int t = 1; t < 10; t++) m = fmaxf(m, sp[nl * 10 + t]);
        sm[nl] = m;
    }
    __syncthreads();
    float m = sm[nl];
    float ps = act ? (__expf(acc.x - m) + __expf(acc.y - m) + __expf(acc.z - m) + __expf(acc.w - m)) : 0.f;
    sp[nl * 10 + j] = ps;
    __syncthreads();
    if (j == 0) {
        float s = 0.f;
        #pragma unroll
        for (int t = 0; t < 10; t++) s += sp[nl * 10 + t];
        sl[nl] = m + __logf(s);
    }
    __syncthreads();
    if (act) {
        float ls = sl[nl];
        int base = v * CD + c4;
        out[base + 0] = acc.x - ls;
        out[base + 1] = acc.y - ls;
        out[base + 2] = acc.z - ls;
        out[base + 3] = acc.w - ls;
    }
}

extern "C" void kernel_launch(void* const* d_in, const int* in_sizes, int n_in,
                              void* d_out, int out_size) {
    const float* x   = (const float*)d_in[0];
    const void*  ei  = d_in[1];
    const float* ea  = (const float*)d_in[2];
    const float* W1  = (const float*)d_in[3];
    const float* b1  = (const float*)d_in[4];
    const float* W2  = (const float*)d_in[5];
    const float* b2  = (const float*)d_in[6];
    float*       out = (float*)d_out;

    k_init   <<<(NN + 255) / 256, 256>>>();
    k_fat1   <<<GB1 + EB1, 256>>>(x, W1, ei, ea);
    k_fat2   <<<2 * NB, 1024>>>();
    k_scan2  <<<1, 128>>>();
    k_scan3  <<<NB, 1024>>>();
    k_fill   <<<(EE + 255) / 256, 256>>>(ea);
    k_agg1g2 <<<(NN + 31) / 32, 512>>>(b1, W2);
    k_agg2   <<<(NN + 31) / 32, 320>>>(b2, out);
}

// round 17
// speedup vs baseline: 1.3150x; 1.2495x over previous
#include <cuda_runtime.h>
#include <cuda_bf16.h>
#include <mma.h>
#include <math.h>
#include <float.h>

using namespace nvcuda;

#define NN 100000
#define EE 1600000
#define FIN 256
#define HD 64
#define CD 40
#define NB 98                 // ceil(NN/1024) scan blocks
#define GB1 782               // gemm1 wmma blocks: ceil(NN/128)
#define EB1 1563              // extract blocks: ceil(EE/1024)

// ---- scratch ----------------------------------------------------------------
__device__ __align__(16) float g_deg[NN];         // deg -> dinv in place
__device__ __align__(16) float g_H1[NN * HD];     // x@W1 fp32
__device__ __align__(16) float g_H2[NN * CD];     // (relu(agg1)) @ W2
__device__ int   g_src[EE];
__device__ int   g_dst[EE];
__device__ int   g_cnt[NN];
__device__ int   g_cur[NN];
__device__ int   g_rowptr[NN + 1];
__device__ int   g_bsum[128];
__device__ __align__(16) int2 g_csr_sn[EE];       // (src, norm-bits) in CSR order

// ---------- K0: init ---------------------------------------------------------
__global__ void k_init() {
    int i = blockIdx.x * blockDim.x + threadIdx.x;
    if (i < NN) { g_deg[i] = 1.0f; g_cnt[i] = 0; }
}

// ---------- K1 (fat): gemm1 (bf16 wmma) | extract+count ----------------------
__global__ void k_fat1(const float* __restrict__ x, const float* __restrict__ W1,
                       const void* __restrict__ ei, const float* __restrict__ w) {
    __shared__ __nv_bfloat16 sA[128 * 24];   // A tile 128 x k16, ldm 24 (48B rows)
    __shared__ __nv_bfloat16 sB[16 * 64];    // W1 tile k16 x 64, ldm 64

    int tid = threadIdx.x;

    if (blockIdx.x < GB1) {
        // --------- tensor-core GEMM1 tile: 128 rows x 64 cols, K=256 ---------
        int rowbase = blockIdx.x * 128;
        int wid = tid >> 5;     // warp 0..7 -> rows wid*16..wid*16+15

        wmma::fragment<wmma::accumulator, 16, 16, 16, float> cf[4];
        #pragma unroll
        for (int j = 0; j < 4; j++) wmma::fill_fragment(cf[j], 0.0f);

        for (int kc = 0; kc < 16; kc++) {
            __syncthreads();
            // load A chunk: 128 rows x 16 k-vals (512 float4 loads, 2/thread)
            #pragma unroll
            for (int i = tid; i < 512; i += 256) {
                int r = i >> 2;
                int q = (i & 3) * 4;
                int row = rowbase + r;
                float4 v = (row < NN) ? *(const float4*)&x[row * FIN + kc * 16 + q]
                                      : make_float4(0.f, 0.f, 0.f, 0.f);
                sA[r * 24 + q + 0] = __float2bfloat16_rn(v.x);
                sA[r * 24 + q + 1] = __float2bfloat16_rn(v.y);
                sA[r * 24 + q + 2] = __float2bfloat16_rn(v.z);
                sA[r * 24 + q + 3] = __float2bfloat16_rn(v.w);
            }
            // load B chunk: 16 x 64 (256 float4 loads, 1/thread)
            {
                int r = tid >> 4;
                int q = (tid & 15) * 4;
                float4 v = *(const float4*)&W1[(kc * 16 + r) * 64 + q];
                sB[r * 64 + q + 0] = __float2bfloat16_rn(v.x);
                sB[r * 64 + q + 1] = __float2bfloat16_rn(v.y);
                sB[r * 64 + q + 2] = __float2bfloat16_rn(v.z);
                sB[r * 64 + q + 3] = __float2bfloat16_rn(v.w);
            }
            __syncthreads();

            wmma::fragment<wmma::matrix_a, 16, 16, 16, __nv_bfloat16, wmma::row_major> af;
            wmma::load_matrix_sync(af, &sA[wid * 16 * 24], 24);
            #pragma unroll
            for (int j = 0; j < 4; j++) {
                wmma::fragment<wmma::matrix_b, 16, 16, 16, __nv_bfloat16, wmma::row_major> bfr;
                wmma::load_matrix_sync(bfr, &sB[j * 16], 64);
                wmma::mma_sync(cf[j], af, bfr, cf[j]);
            }
        }
        int wrow = rowbase + wid * 16;
        if (wrow + 16 <= NN) {     // NN % 32 == 0: all-or-nothing per warp
            #pragma unroll
            for (int j = 0; j < 4; j++)
                wmma::store_matrix_sync(&g_H1[wrow * HD + j * 16], cf[j], HD, wmma::mem_row_major);
        }
    } else {
        // ---------------- extract + count: 1024 edges per block --------------
        int base = (blockIdx.x - GB1) * 1024;
        const long long* p64 = (const long long*)ei;
        const int*       p32 = (const int*)ei;

        long long v = p64[base + tid];
        int bad = (v < 0 || v >= NN) ? 1 : 0;
        int is64 = !__syncthreads_or(bad);

        #pragma unroll
        for (int i = 0; i < 4; i++) {
            int e = base + i * 256 + tid;
            if (e < EE) {
                int s, d;
                if (is64) { s = (int)p64[e]; d = (int)p64[EE + e]; }
                else      { s = p32[e];      d = p32[EE + e]; }
                g_src[e] = s; g_dst[e] = d;
                atomicAdd(&g_cnt[d], 1);
                atomicAdd(&g_deg[d], w[e]);
            }
        }
    }
}

// ---------- K2 (fat): scan1 | dinv + cur=0 -----------------------------------
__global__ void k_fat2() {
    int b = blockIdx.x, t = threadIdx.x;
    if (b < NB) {
        __shared__ int s[1024];
        int i = b * 1024 + t;
        int v = (i < NN) ? g_cnt[i] : 0;
        s[t] = v; __syncthreads();
        for (int off = 1; off < 1024; off <<= 1) {
            int add = (t >= off) ? s[t - off] : 0;
            __syncthreads();
            s[t] += add;
            __syncthreads();
        }
        if (i < NN) g_rowptr[i + 1] = s[t];
        if (t == 1023) g_bsum[b] = s[t];
    } else {
        int i = (b - NB) * 1024 + t;
        if (i < NN) {
            float d = g_deg[i];
            g_deg[i] = (d > 0.f) ? rsqrtf(d) : 0.f;
            g_cur[i] = 0;
        }
    }
}

// ---------- K3/K4: scan finish -----------------------------------------------
__global__ void k_scan2() {
    __shared__ int s[128];
    int t = threadIdx.x;
    int v = (t < NB) ? g_bsum[t] : 0;
    s[t] = v; __syncthreads();
    for (int off = 1; off < 128; off <<= 1) {
        int add = (t >= off) ? s[t - off] : 0;
        __syncthreads();
        s[t] += add;
        __syncthreads();
    }
    if (t < NB) g_bsum[t] = s[t];
}
__global__ void k_scan3() {
    int b = blockIdx.x, t = threadIdx.x;
    int i = b * 1024 + t;
    if (b > 0 && i < NN) g_rowptr[i + 1] += g_bsum[b - 1];
    if (b == 0 && t == 0) g_rowptr[0] = 0;
}

// ---------- K5: fill CSR (packed src+norm) -----------------------------------
__global__ void k_fill(const float* __restrict__ w) {
    int e = blockIdx.x * blockDim.x + threadIdx.x;
    if (e < EE) {
        int s = g_src[e];
        int d = g_dst[e];
        float nrm = g_deg[s] * w[e] * g_deg[d];
        int p = atomicAdd(&g_cur[d], 1);
        g_csr_sn[g_rowptr[d] + p] = make_int2(s, __float_as_int(nrm));
    }
}

// ---------- K6: agg1 + relu + GEMM2, fused -----------------------------------
__global__ void k_agg1g2(const float* __restrict__ b1, const float* __restrict__ W2) {
    __shared__ float sH[32 * 68];
    __shared__ float sW2[64 * 40];

    int tid = threadIdx.x;
    int nl  = tid >> 4;
    int c4  = (tid & 15) * 4;
    int v   = blockIdx.x * 32 + nl;

    #pragma unroll
    for (int i = tid; i < 64 * 40; i += 512)
        sW2[i] = W2[i];

    if (v < NN) {
        int e   = g_rowptr[v];
        int end = g_rowptr[v + 1];
        float4 acc = make_float4(0.f, 0.f, 0.f, 0.f);

        for (; e + 4 <= end; e += 4) {
            int2 sn0 = g_csr_sn[e],     sn1 = g_csr_sn[e + 1];
            int2 sn2 = g_csr_sn[e + 2], sn3 = g_csr_sn[e + 3];
            float4 h0 = *(const float4*)&g_H1[sn0.x * HD + c4];
            float4 h1 = *(const float4*)&g_H1[sn1.x * HD + c4];
            float4 h2 = *(const float4*)&g_H1[sn2.x * HD + c4];
            float4 h3 = *(const float4*)&g_H1[sn3.x * HD + c4];
            float n0 = __int_as_float(sn0.y), n1 = __int_as_float(sn1.y);
            float n2 = __int_as_float(sn2.y), n3 = __int_as_float(sn3.y);
            acc.x += h0.x * n0 + h1.x * n1 + h2.x * n2 + h3.x * n3;
            acc.y += h0.y * n0 + h1.y * n1 + h2.y * n2 + h3.y * n3;
            acc.z += h0.z * n0 + h1.z * n1 + h2.z * n2 + h3.z * n3;
            acc.w += h0.w * n0 + h1.w * n1 + h2.w * n2 + h3.w * n3;
        }
        for (; e < end; e++) {
            int2 sn = g_csr_sn[e];
            float n = __int_as_float(sn.y);
            float4 h = *(const float4*)&g_H1[sn.x * HD + c4];
            acc.x += h.x * n; acc.y += h.y * n;
            acc.z += h.z * n; acc.w += h.w * n;
        }

        float di = g_deg[v];
        float sn2 = di * di;
        float4 hs = *(const float4*)&g_H1[v * HD + c4];
        float4 bb = *(const float4*)&b1[c4];
        sH[nl * 68 + c4 + 0] = fmaxf(acc.x + hs.x * sn2 + bb.x, 0.f);
        sH[nl * 68 + c4 + 1] = fmaxf(acc.y + hs.y * sn2 + bb.y, 0.f);
        sH[nl * 68 + c4 + 2] = fmaxf(acc.z + hs.z * sn2 + bb.z, 0.f);
        sH[nl * 68 + c4 + 3] = fmaxf(acc.w + hs.w * sn2 + bb.w, 0.f);
    }
    __syncthreads();

    if (tid < 320) {
        int n2 = tid / 10;
        int cg = tid % 10;
        int vv = blockIdx.x * 32 + n2;
        if (vv < NN) {
            float4 a = make_float4(0.f, 0.f, 0.f, 0.f);
            const float* hrow = &sH[n2 * 68];
            #pragma unroll
            for (int k = 0; k < 64; k++) {
                float xv = hrow[k];
                float4 wv = *(const float4*)&sW2[k * 40 + cg * 4];
                a.x += xv * wv.x; a.y += xv * wv.y;
                a.z += xv * wv.z; a.w += xv * wv.w;
            }
            *(float4*)&g_H2[vv * CD + cg * 4] = a;
        }
    }
}

// ---------- K7: agg2 (fp32 gather) + self + bias + log_softmax ---------------
__global__ void k_agg2(const float* __restrict__ b2, float* __restrict__ out) {
    __shared__ float sp[32 * 10];
    __shared__ float sm[32];
    __shared__ float sl[32];

    int tid = threadIdx.x;
    int nl = tid / 10;
    int j  = tid % 10;
    int v  = blockIdx.x * 32 + nl;
    bool act = (v < NN);
    int c4 = j * 4;

    float4 acc = make_float4(0.f, 0.f, 0.f, 0.f);
    if (act) {
        int e   = g_rowptr[v];
        int end = g_rowptr[v + 1];
        for (; e + 4 <= end; e += 4) {
            int2 sn0 = g_csr_sn[e],     sn1 = g_csr_sn[e + 1];
            int2 sn2 = g_csr_sn[e + 2], sn3 = g_csr_sn[e + 3];
            float4 h0 = *(const float4*)&g_H2[sn0.x * CD + c4];
            float4 h1 = *(const float4*)&g_H2[sn1.x * CD + c4];
            float4 h2 = *(const float4*)&g_H2[sn2.x * CD + c4];
            float4 h3 = *(const float4*)&g_H2[sn3.x * CD + c4];
            float n0 = __int_as_float(sn0.y), n1 = __int_as_float(sn1.y);
            float n2 = __int_as_float(sn2.y), n3 = __int_as_float(sn3.y);
            acc.x += h0.x * n0 + h1.x * n1 + h2.x * n2 + h3.x * n3;
            acc.y += h0.y * n0 + h1.y * n1 + h2.y * n2 + h3.y * n3;
            acc.z += h0.z * n0 + h1.z * n1 + h2.z * n2 + h3.z * n3;
            acc.w += h0.w * n0 + h1.w * n1 + h2.w * n2 + h3.w * n3;
        }
        for (; e < end; e++) {
            int2 sn = g_csr_sn[e];
            float n = __int_as_float(sn.y);
            float4 h = *(const float4*)&g_H2[sn.x * CD + c4];
            acc.x += h.x * n; acc.y += h.y * n;
            acc.z += h.z * n; acc.w += h.w * n;
        }
        float di = g_deg[v];
        float sn2 = di * di;
        float4 hs = *(const float4*)&g_H2[v * CD + c4];
        float4 bb = *(const float4*)&b2[c4];
        acc.x += hs.x * sn2 + bb.x;
        acc.y += hs.y * sn2 + bb.y;
        acc.z += hs.z * sn2 + bb.z;
        acc.w += hs.w * sn2 + bb.w;
    }

    float pm = fmaxf(fmaxf(acc.x, acc.y), fmaxf(acc.z, acc.w));
    sp[nl * 10 + j] = act ? pm : -FLT_MAX;
    __syncthreads();
    if (j == 0) {
        float m = sp[nl * 10];
        #pragma unroll
        for (int t = 1; t < 10; t++) m = fmaxf(m, sp[nl * 10 + t]);
        sm[nl] = m;
    }
    __syncthreads();
    float m = sm[nl];
    float ps = act ? (__expf(acc.x - m) + __expf(acc.y - m) + __expf(acc.z - m) + __expf(acc.w - m)) : 0.f;
    sp[nl * 10 + j] = ps;
    __syncthreads();
    if (j == 0) {
        float s = 0.f;
        #pragma unroll
        for (int t = 0; t < 10; t++) s += sp[nl * 10 + t];
        sl[nl] = m + __logf(s);
    }
    __syncthreads();
    if (act) {
        float ls = sl[nl];
        int base = v * CD + c4;
        out[base + 0] = acc.x - ls;
        out[base + 1] = acc.y - ls;
        out[base + 2] = acc.z - ls;
        out[base + 3] = acc.w - ls;
    }
}

extern "C" void kernel_launch(void* const* d_in, const int* in_sizes, int n_in,
                              void* d_out, int out_size) {
    const float* x   = (const float*)d_in[0];
    const void*  ei  = d_in[1];
    const float* ea  = (const float*)d_in[2];
    const float* W1  = (const float*)d_in[3];
    const float* b1  = (const float*)d_in[4];
    const float* W2  = (const float*)d_in[5];
    const float* b2  = (const float*)d_in[6];
    float*       out = (float*)d_out;

    k_init   <<<(NN + 255) / 256, 256>>>();
    k_fat1   <<<GB1 + EB1, 256>>>(x, W1, ei, ea);
    k_fat2   <<<2 * NB, 1024>>>();
    k_scan2  <<<1, 128>>>();
    k_scan3  <<<NB, 1024>>>();
    k_fill   <<<(EE + 255) / 256, 256>>>(ea);
    k_agg1g2 <<<(NN + 31) / 32, 512>>>(b1, W2);
    k_agg2   <<<(NN + 31) / 32, 320>>>(b2, out);
}